// round 2
// baseline (speedup 1.0000x reference)
#include <cuda_runtime.h>
#include <math.h>

// Problem constants
#define BATCH 512
#define NSEG 64
#define HID 1024
#define ATTD 128

// ---------------- scratch (device globals; no allocation allowed) ----------------
__device__ float g_act1[512 * 8 * 64 * 64];   // after layer1 (pooled)
__device__ float g_act2[512 * 16 * 32 * 32];
__device__ float g_act3[512 * 32 * 16 * 16];
__device__ float g_act4[512 * 64 * 8 * 8];
__device__ float g_act5[512 * 128 * 4 * 4];   // = emb input (512 x 2048)
__device__ float g_emb[512 * 1024];
__device__ float g_logits[512];

// ---------------- fused conv(5x5,pad2) + maxpool(2) + relu ----------------
// Each thread: one pooled output pixel x NCO output channels.
// acc[4][NCO]: 2x2 conv window accumulated simultaneously so each weight
// load is reused 4x and each input load NCO x.
template <int CIN, int COUT_BLK, int NCO, int TP, int IN_HW, bool W_SMEM, int NTHREADS>
__global__ __launch_bounds__(NTHREADS)
void conv_pool_relu(const float* __restrict__ in, const float* __restrict__ w,
                    const float* __restrict__ bias, float* __restrict__ out,
                    int cout_total)
{
    constexpr int OUT_HW = IN_HW / 2;
    constexpr int TILES  = OUT_HW / TP;
    constexpr int PATCH  = 2 * TP + 4;
    constexpr int PS     = PATCH + 1;            // odd row stride -> no LDS conflicts
    constexpr int CG     = COUT_BLK / NCO;

    extern __shared__ float smem[];
    float* ins = smem;                            // CIN * PATCH * PS
    float* wsm = smem + CIN * PATCH * PS;         // COUT_BLK * CIN * 25 (if W_SMEM)

    const int tid     = threadIdx.x;
    const int n       = blockIdx.z;
    const int co0_blk = blockIdx.y * COUT_BLK;
    const int ty      = blockIdx.x / TILES;
    const int tx      = blockIdx.x % TILES;
    const int y0      = ty * TP * 2 - 2;          // patch origin in input coords
    const int x0      = tx * TP * 2 - 2;

    // stage input patch (zero-padded halo)
    const float* inb = in + (size_t)n * CIN * IN_HW * IN_HW;
    for (int idx = tid; idx < CIN * PATCH * PATCH; idx += NTHREADS) {
        int ci  = idx / (PATCH * PATCH);
        int rem = idx % (PATCH * PATCH);
        int r   = rem / PATCH;
        int cc  = rem % PATCH;
        int gy  = y0 + r, gx = x0 + cc;
        float v = 0.f;
        if (gy >= 0 && gy < IN_HW && gx >= 0 && gx < IN_HW)
            v = inb[(ci * IN_HW + gy) * IN_HW + gx];
        ins[(ci * PATCH + r) * PS + cc] = v;
    }
    if (W_SMEM) {
        const float* wb = w + (size_t)co0_blk * CIN * 25;
        for (int idx = tid; idx < COUT_BLK * CIN * 25; idx += NTHREADS)
            wsm[idx] = wb[idx];
    }
    __syncthreads();

    const int ppx = tid % TP;
    const int ppy = (tid / TP) % TP;
    const int cg  = tid / (TP * TP);
    const int co0 = co0_blk + cg * NCO;

    float acc[4][NCO];
#pragma unroll
    for (int c = 0; c < NCO; c++) {
        float bv = bias[co0 + c];
        acc[0][c] = bv; acc[1][c] = bv; acc[2][c] = bv; acc[3][c] = bv;
    }

#pragma unroll 1
    for (int ci = 0; ci < CIN; ci++) {
        const float* insc = ins + ci * PATCH * PS;
#pragma unroll
        for (int ky = 0; ky < 5; ky++) {
#pragma unroll
            for (int kx = 0; kx < 5; kx++) {
                float wv[NCO];
#pragma unroll
                for (int c = 0; c < NCO; c++) {
                    if (W_SMEM)
                        wv[c] = wsm[((cg * NCO + c) * CIN + ci) * 25 + ky * 5 + kx];
                    else
                        wv[c] = __ldg(&w[((size_t)(co0 + c) * CIN + ci) * 25 + ky * 5 + kx]);
                }
#pragma unroll
                for (int cy = 0; cy < 2; cy++)
#pragma unroll
                for (int cx = 0; cx < 2; cx++) {
                    float v = insc[(2 * ppy + cy + ky) * PS + (2 * ppx + cx + kx)];
#pragma unroll
                    for (int c = 0; c < NCO; c++)
                        acc[cy * 2 + cx][c] = fmaf(v, wv[c], acc[cy * 2 + cx][c]);
                }
            }
        }
    }

    const int oy = ty * TP + ppy;
    const int ox = tx * TP + ppx;
    float* outb = out + (size_t)n * cout_total * OUT_HW * OUT_HW;
#pragma unroll
    for (int c = 0; c < NCO; c++) {
        float m = fmaxf(fmaxf(acc[0][c], acc[1][c]), fmaxf(acc[2][c], acc[3][c]));
        m = fmaxf(m, 0.f);
        outb[((size_t)(co0 + c) * OUT_HW + oy) * OUT_HW + ox] = m;
    }
}

// ---------------- FC: emb = act5(512x2048) @ fc_w(1024x2048)^T + fc_b ----------------
__global__ __launch_bounds__(256)
void fc_gemm(const float* __restrict__ A, const float* __restrict__ W,
             const float* __restrict__ bias, float* __restrict__ C)
{
    constexpr int N = 1024, K = 2048, BM = 64, BN = 64, BK = 16;
    __shared__ float As[BK][BM];
    __shared__ float Ws[BK][BN];

    const int tid = threadIdx.x;
    const int bm = blockIdx.y * BM, bn = blockIdx.x * BN;
    const int tx = tid % 16, ty = tid / 16;
    const int lr = tid / 4, lc = tid % 4;   // staging coords

    float acc[4][4] = {};

    for (int k0 = 0; k0 < K; k0 += BK) {
        float4 a4 = *(const float4*)&A[(size_t)(bm + lr) * K + k0 + lc * 4];
        float4 w4 = *(const float4*)&W[(size_t)(bn + lr) * K + k0 + lc * 4];
        As[lc * 4 + 0][lr] = a4.x; As[lc * 4 + 1][lr] = a4.y;
        As[lc * 4 + 2][lr] = a4.z; As[lc * 4 + 3][lr] = a4.w;
        Ws[lc * 4 + 0][lr] = w4.x; Ws[lc * 4 + 1][lr] = w4.y;
        Ws[lc * 4 + 2][lr] = w4.z; Ws[lc * 4 + 3][lr] = w4.w;
        __syncthreads();
#pragma unroll
        for (int kk = 0; kk < BK; kk++) {
            float4 av = *(const float4*)&As[kk][ty * 4];
            float4 wv = *(const float4*)&Ws[kk][tx * 4];
            acc[0][0] += av.x * wv.x; acc[0][1] += av.x * wv.y; acc[0][2] += av.x * wv.z; acc[0][3] += av.x * wv.w;
            acc[1][0] += av.y * wv.x; acc[1][1] += av.y * wv.y; acc[1][2] += av.y * wv.z; acc[1][3] += av.y * wv.w;
            acc[2][0] += av.z * wv.x; acc[2][1] += av.z * wv.y; acc[2][2] += av.z * wv.z; acc[2][3] += av.z * wv.w;
            acc[3][0] += av.w * wv.x; acc[3][1] += av.w * wv.y; acc[3][2] += av.w * wv.z; acc[3][3] += av.w * wv.w;
        }
        __syncthreads();
    }

#pragma unroll
    for (int i = 0; i < 4; i++)
#pragma unroll
        for (int j = 0; j < 4; j++)
            C[(size_t)(bm + ty * 4 + i) * N + bn + tx * 4 + j] = acc[i][j] + bias[bn + tx * 4 + j];
}

// ---------------- attention logits: tanh(emb@W1^T+b1)@W2^T+b2 ----------------
// One block handles 8 batch rows; 128 threads = 128 attention units.
__global__ __launch_bounds__(128)
void attention_kernel(const float* __restrict__ emb, const float* __restrict__ w1,
                      const float* __restrict__ b1, const float* __restrict__ w2,
                      const float* __restrict__ b2, float* __restrict__ logits)
{
    __shared__ float es[8][HID];      // 32 KB
    __shared__ float red[128];
    const int tid = threadIdx.x;
    const int r0 = blockIdx.x * 8;

    for (int idx = tid; idx < 8 * HID; idx += 128)
        es[idx / HID][idx % HID] = emb[(size_t)(r0 + idx / HID) * HID + idx % HID];
    __syncthreads();

    const int j = tid;
    float acc[8];
    float bj = b1[j];
#pragma unroll
    for (int r = 0; r < 8; r++) acc[r] = bj;

    for (int k = 0; k < HID; k++) {
        float wv = w1[(size_t)j * HID + k];
#pragma unroll
        for (int r = 0; r < 8; r++) acc[r] = fmaf(es[r][k], wv, acc[r]);
    }

    const float w2j = w2[j];
    for (int r = 0; r < 8; r++) {
        red[tid] = tanhf(acc[r]) * w2j;
        __syncthreads();
        for (int s = 64; s > 0; s >>= 1) {
            if (tid < s) red[tid] += red[tid + s];
            __syncthreads();
        }
        if (tid == 0) logits[r0 + r] = red[0] + b2[0];
        __syncthreads();
    }
}

// ---------------- segment softmax + weighted aggregate + classifier ----------------
// case_ids are sorted; one block per segment.
__global__ __launch_bounds__(256)
void segment_head(const float* __restrict__ logits, const int* __restrict__ ids,
                  const float* __restrict__ emb, const float* __restrict__ clf_w,
                  const float* __restrict__ clf_b, float* __restrict__ out)
{
    const int c = blockIdx.x, tid = threadIdx.x;
    __shared__ float red[256];
    __shared__ int ired[256];
    __shared__ float wgt[512];
    __shared__ int s_lo, s_hi;

    int llo = 0, lhi = 0;
    for (int i = tid; i < BATCH; i += 256) {
        int id = ids[i];
        llo += (id < c);
        lhi += (id <= c);
    }
    ired[tid] = llo; __syncthreads();
    for (int s = 128; s > 0; s >>= 1) { if (tid < s) ired[tid] += ired[tid + s]; __syncthreads(); }
    if (tid == 0) s_lo = ired[0];
    __syncthreads();
    ired[tid] = lhi; __syncthreads();
    for (int s = 128; s > 0; s >>= 1) { if (tid < s) ired[tid] += ired[tid + s]; __syncthreads(); }
    if (tid == 0) s_hi = ired[0];
    __syncthreads();

    const int lo = s_lo, hi = s_hi, nn = hi - lo;

    // segment max
    float m = -INFINITY;
    for (int i = lo + tid; i < hi; i += 256) m = fmaxf(m, logits[i]);
    red[tid] = m; __syncthreads();
    for (int s = 128; s > 0; s >>= 1) { if (tid < s) red[tid] = fmaxf(red[tid], red[tid + s]); __syncthreads(); }
    const float segmax = red[0];
    __syncthreads();

    // exp + denom
    float ls = 0.f;
    for (int i = lo + tid; i < hi; i += 256) {
        float e = expf(logits[i] - segmax);
        wgt[i - lo] = e;
        ls += e;
    }
    red[tid] = ls; __syncthreads();
    for (int s = 128; s > 0; s >>= 1) { if (tid < s) red[tid] += red[tid + s]; __syncthreads(); }
    const float denom = red[0];
    __syncthreads();

    for (int i = tid; i < nn; i += 256) wgt[i] /= denom;
    __syncthreads();

    // aggr[h] = sum_k wgt[k]*emb[lo+k][h];  sc = aggr . clf_w
    float sc = 0.f;
    for (int h = tid; h < HID; h += 256) {
        float a = 0.f;
        for (int k = 0; k < nn; k++)
            a = fmaf(wgt[k], emb[(size_t)(lo + k) * HID + h], a);
        sc = fmaf(a, clf_w[h], sc);
    }
    red[tid] = sc; __syncthreads();
    for (int s = 128; s > 0; s >>= 1) { if (tid < s) red[tid] += red[tid + s]; __syncthreads(); }
    if (tid == 0) out[c] = 1.f / (1.f + expf(-(red[0] + clf_b[0])));
}

// ---------------- launch ----------------
extern "C" void kernel_launch(void* const* d_in, const int* in_sizes, int n_in,
                              void* d_out, int out_size)
{
    const float* data = (const float*)d_in[0];
    const int*   cid  = (const int*)d_in[1];
    const float* cw1 = (const float*)d_in[2];  const float* cb1 = (const float*)d_in[3];
    const float* cw2 = (const float*)d_in[4];  const float* cb2 = (const float*)d_in[5];
    const float* cw3 = (const float*)d_in[6];  const float* cb3 = (const float*)d_in[7];
    const float* cw4 = (const float*)d_in[8];  const float* cb4 = (const float*)d_in[9];
    const float* cw5 = (const float*)d_in[10]; const float* cb5 = (const float*)d_in[11];
    const float* fcw = (const float*)d_in[12]; const float* fcb = (const float*)d_in[13];
    const float* aw1 = (const float*)d_in[14]; const float* ab1 = (const float*)d_in[15];
    const float* aw2 = (const float*)d_in[16]; const float* ab2 = (const float*)d_in[17];
    const float* clw = (const float*)d_in[18]; const float* clb = (const float*)d_in[19];
    float* out = (float*)d_out;

    float *a1, *a2, *a3, *a4, *a5, *emb, *lg;
    cudaGetSymbolAddress((void**)&a1, g_act1);
    cudaGetSymbolAddress((void**)&a2, g_act2);
    cudaGetSymbolAddress((void**)&a3, g_act3);
    cudaGetSymbolAddress((void**)&a4, g_act4);
    cudaGetSymbolAddress((void**)&a5, g_act5);
    cudaGetSymbolAddress((void**)&emb, g_emb);
    cudaGetSymbolAddress((void**)&lg, g_logits);

    // dynamic smem sizes (bytes): ins = CIN*PATCH*(PATCH+1), w = COUT_BLK*CIN*25
    const int SM1 = (3 * 36 * 37 + 8 * 3 * 25) * 4;     // 18384
    const int SM2 = (8 * 36 * 37 + 16 * 8 * 25) * 4;    // 55424
    const int SM3 = (16 * 36 * 37 + 16 * 16 * 25) * 4;  // 110848
    const int SM4 = (32 * 20 * 21 + 32 * 32 * 25) * 4;  // 156160
    const int SM5 = (64 * 12 * 13) * 4;                 // 39936

    cudaFuncSetAttribute((const void*)conv_pool_relu<8, 16, 8, 16, 64, true, 512>,
                         cudaFuncAttributeMaxDynamicSharedMemorySize, SM2);
    cudaFuncSetAttribute((const void*)conv_pool_relu<16, 16, 8, 16, 32, true, 512>,
                         cudaFuncAttributeMaxDynamicSharedMemorySize, SM3);
    cudaFuncSetAttribute((const void*)conv_pool_relu<32, 32, 8, 8, 16, true, 256>,
                         cudaFuncAttributeMaxDynamicSharedMemorySize, SM4);

    // L1: 3->8, 128->64.  grid (4x4 tiles, 1, 512)
    conv_pool_relu<3, 8, 8, 16, 128, true, 256>
        <<<dim3(16, 1, 512), 256, SM1>>>(data, cw1, cb1, a1, 8);
    // L2: 8->16, 64->32.  grid (2x2 tiles, 1, 512)
    conv_pool_relu<8, 16, 8, 16, 64, true, 512>
        <<<dim3(4, 1, 512), 512, SM2>>>(a1, cw2, cb2, a2, 16);
    // L3: 16->32, 32->16. grid (1, 2 cout-groups, 512)
    conv_pool_relu<16, 16, 8, 16, 32, true, 512>
        <<<dim3(1, 2, 512), 512, SM3>>>(a2, cw3, cb3, a3, 32);
    // L4: 32->64, 16->8.  grid (1, 2, 512)
    conv_pool_relu<32, 32, 8, 8, 16, true, 256>
        <<<dim3(1, 2, 512), 256, SM4>>>(a3, cw4, cb4, a4, 64);
    // L5: 64->128, 8->4.  grid (1, 1, 512); weights via L2 (__ldg)
    conv_pool_relu<64, 128, 8, 4, 8, false, 256>
        <<<dim3(1, 1, 512), 256, SM5>>>(a4, cw5, cb5, a5, 128);

    // FC: (512x2048)@(1024x2048)^T
    fc_gemm<<<dim3(16, 8), 256>>>(a5, fcw, fcb, emb);

    // attention logits
    attention_kernel<<<64, 128>>>(emb, aw1, ab1, aw2, ab2, lg);

    // segment softmax + aggregate + classifier
    segment_head<<<64, 256>>>(lg, cid, emb, clw, clb, out);
}

// round 3
// speedup vs baseline: 1.0016x; 1.0016x over previous
#include <cuda_runtime.h>
#include <math.h>

// Problem constants
#define BATCH 512
#define NSEG 64
#define HID 1024
#define ATTD 128

// ---------------- scratch (device globals; no allocation allowed) ----------------
__device__ float g_act1[512 * 8 * 64 * 64];   // after layer1 (pooled)
__device__ float g_act2[512 * 16 * 32 * 32];
__device__ float g_act3[512 * 32 * 16 * 16];
__device__ float g_act4[512 * 64 * 8 * 8];
__device__ float g_act5[512 * 128 * 4 * 4];   // = emb input (512 x 2048)
__device__ float g_emb[512 * 1024];
__device__ float g_logits[512];

// ---------------- fused conv(5x5,pad2) + maxpool(2) + relu ----------------
// Each thread: one pooled output pixel x NCO output channels.
// acc[4][NCO]: 2x2 conv window accumulated simultaneously so each weight
// load is reused 4x and each input load NCO x.
template <int CIN, int COUT_BLK, int NCO, int TP, int IN_HW, bool W_SMEM, int NTHREADS>
__global__ __launch_bounds__(NTHREADS)
void conv_pool_relu(const float* __restrict__ in, const float* __restrict__ w,
                    const float* __restrict__ bias, float* __restrict__ out,
                    int cout_total)
{
    constexpr int OUT_HW = IN_HW / 2;
    constexpr int TILES  = OUT_HW / TP;
    constexpr int PATCH  = 2 * TP + 4;
    constexpr int PS     = PATCH + 1;            // odd row stride -> no LDS conflicts
    constexpr int CG     = COUT_BLK / NCO;

    extern __shared__ float smem[];
    float* ins = smem;                            // CIN * PATCH * PS
    float* wsm = smem + CIN * PATCH * PS;         // COUT_BLK * CIN * 25 (if W_SMEM)

    const int tid     = threadIdx.x;
    const int n       = blockIdx.z;
    const int co0_blk = blockIdx.y * COUT_BLK;
    const int ty      = blockIdx.x / TILES;
    const int tx      = blockIdx.x % TILES;
    const int y0      = ty * TP * 2 - 2;          // patch origin in input coords
    const int x0      = tx * TP * 2 - 2;

    // stage input patch (zero-padded halo)
    const float* inb = in + (size_t)n * CIN * IN_HW * IN_HW;
    for (int idx = tid; idx < CIN * PATCH * PATCH; idx += NTHREADS) {
        int ci  = idx / (PATCH * PATCH);
        int rem = idx % (PATCH * PATCH);
        int r   = rem / PATCH;
        int cc  = rem % PATCH;
        int gy  = y0 + r, gx = x0 + cc;
        float v = 0.f;
        if (gy >= 0 && gy < IN_HW && gx >= 0 && gx < IN_HW)
            v = inb[(ci * IN_HW + gy) * IN_HW + gx];
        ins[(ci * PATCH + r) * PS + cc] = v;
    }
    if (W_SMEM) {
        const float* wb = w + (size_t)co0_blk * CIN * 25;
        for (int idx = tid; idx < COUT_BLK * CIN * 25; idx += NTHREADS)
            wsm[idx] = wb[idx];
    }
    __syncthreads();

    const int ppx = tid % TP;
    const int ppy = (tid / TP) % TP;
    const int cg  = tid / (TP * TP);
    const int co0 = co0_blk + cg * NCO;

    float acc[4][NCO];
#pragma unroll
    for (int c = 0; c < NCO; c++) {
        float bv = bias[co0 + c];
        acc[0][c] = bv; acc[1][c] = bv; acc[2][c] = bv; acc[3][c] = bv;
    }

#pragma unroll 1
    for (int ci = 0; ci < CIN; ci++) {
        const float* insc = ins + ci * PATCH * PS;
#pragma unroll
        for (int ky = 0; ky < 5; ky++) {
#pragma unroll
            for (int kx = 0; kx < 5; kx++) {
                float wv[NCO];
#pragma unroll
                for (int c = 0; c < NCO; c++) {
                    if (W_SMEM)
                        wv[c] = wsm[((cg * NCO + c) * CIN + ci) * 25 + ky * 5 + kx];
                    else
                        wv[c] = __ldg(&w[((size_t)(co0 + c) * CIN + ci) * 25 + ky * 5 + kx]);
                }
#pragma unroll
                for (int cy = 0; cy < 2; cy++)
#pragma unroll
                for (int cx = 0; cx < 2; cx++) {
                    float v = insc[(2 * ppy + cy + ky) * PS + (2 * ppx + cx + kx)];
#pragma unroll
                    for (int c = 0; c < NCO; c++)
                        acc[cy * 2 + cx][c] = fmaf(v, wv[c], acc[cy * 2 + cx][c]);
                }
            }
        }
    }

    const int oy = ty * TP + ppy;
    const int ox = tx * TP + ppx;
    float* outb = out + (size_t)n * cout_total * OUT_HW * OUT_HW;
#pragma unroll
    for (int c = 0; c < NCO; c++) {
        float m = fmaxf(fmaxf(acc[0][c], acc[1][c]), fmaxf(acc[2][c], acc[3][c]));
        m = fmaxf(m, 0.f);
        outb[((size_t)(co0 + c) * OUT_HW + oy) * OUT_HW + ox] = m;
    }
}

// ---------------- FC: emb = act5(512x2048) @ fc_w(1024x2048)^T + fc_b ----------------
__global__ __launch_bounds__(256)
void fc_gemm(const float* __restrict__ A, const float* __restrict__ W,
             const float* __restrict__ bias, float* __restrict__ C)
{
    constexpr int N = 1024, K = 2048, BM = 64, BN = 64, BK = 16;
    __shared__ float As[BK][BM];
    __shared__ float Ws[BK][BN];

    const int tid = threadIdx.x;
    const int bm = blockIdx.y * BM, bn = blockIdx.x * BN;
    const int tx = tid % 16, ty = tid / 16;
    const int lr = tid / 4, lc = tid % 4;   // staging coords

    float acc[4][4] = {};

    for (int k0 = 0; k0 < K; k0 += BK) {
        float4 a4 = *(const float4*)&A[(size_t)(bm + lr) * K + k0 + lc * 4];
        float4 w4 = *(const float4*)&W[(size_t)(bn + lr) * K + k0 + lc * 4];
        As[lc * 4 + 0][lr] = a4.x; As[lc * 4 + 1][lr] = a4.y;
        As[lc * 4 + 2][lr] = a4.z; As[lc * 4 + 3][lr] = a4.w;
        Ws[lc * 4 + 0][lr] = w4.x; Ws[lc * 4 + 1][lr] = w4.y;
        Ws[lc * 4 + 2][lr] = w4.z; Ws[lc * 4 + 3][lr] = w4.w;
        __syncthreads();
#pragma unroll
        for (int kk = 0; kk < BK; kk++) {
            float4 av = *(const float4*)&As[kk][ty * 4];
            float4 wv = *(const float4*)&Ws[kk][tx * 4];
            acc[0][0] += av.x * wv.x; acc[0][1] += av.x * wv.y; acc[0][2] += av.x * wv.z; acc[0][3] += av.x * wv.w;
            acc[1][0] += av.y * wv.x; acc[1][1] += av.y * wv.y; acc[1][2] += av.y * wv.z; acc[1][3] += av.y * wv.w;
            acc[2][0] += av.z * wv.x; acc[2][1] += av.z * wv.y; acc[2][2] += av.z * wv.z; acc[2][3] += av.z * wv.w;
            acc[3][0] += av.w * wv.x; acc[3][1] += av.w * wv.y; acc[3][2] += av.w * wv.z; acc[3][3] += av.w * wv.w;
        }
        __syncthreads();
    }

#pragma unroll
    for (int i = 0; i < 4; i++)
#pragma unroll
        for (int j = 0; j < 4; j++)
            C[(size_t)(bm + ty * 4 + i) * N + bn + tx * 4 + j] = acc[i][j] + bias[bn + tx * 4 + j];
}

// ---------------- attention logits: tanh(emb@W1^T+b1)@W2^T+b2 ----------------
// One block handles 8 batch rows; 128 threads = 128 attention units.
__global__ __launch_bounds__(128)
void attention_kernel(const float* __restrict__ emb, const float* __restrict__ w1,
                      const float* __restrict__ b1, const float* __restrict__ w2,
                      const float* __restrict__ b2, float* __restrict__ logits)
{
    __shared__ float es[8][HID];      // 32 KB
    __shared__ float red[128];
    const int tid = threadIdx.x;
    const int r0 = blockIdx.x * 8;

    for (int idx = tid; idx < 8 * HID; idx += 128)
        es[idx / HID][idx % HID] = emb[(size_t)(r0 + idx / HID) * HID + idx % HID];
    __syncthreads();

    const int j = tid;
    float acc[8];
    float bj = b1[j];
#pragma unroll
    for (int r = 0; r < 8; r++) acc[r] = bj;

    for (int k = 0; k < HID; k++) {
        float wv = w1[(size_t)j * HID + k];
#pragma unroll
        for (int r = 0; r < 8; r++) acc[r] = fmaf(es[r][k], wv, acc[r]);
    }

    const float w2j = w2[j];
    for (int r = 0; r < 8; r++) {
        red[tid] = tanhf(acc[r]) * w2j;
        __syncthreads();
        for (int s = 64; s > 0; s >>= 1) {
            if (tid < s) red[tid] += red[tid + s];
            __syncthreads();
        }
        if (tid == 0) logits[r0 + r] = red[0] + b2[0];
        __syncthreads();
    }
}

// ---------------- segment softmax + weighted aggregate + classifier ----------------
// case_ids are sorted; one block per segment.
__global__ __launch_bounds__(256)
void segment_head(const float* __restrict__ logits, const int* __restrict__ ids,
                  const float* __restrict__ emb, const float* __restrict__ clf_w,
                  const float* __restrict__ clf_b, float* __restrict__ out)
{
    const int c = blockIdx.x, tid = threadIdx.x;
    __shared__ float red[256];
    __shared__ int ired[256];
    __shared__ float wgt[512];
    __shared__ int s_lo, s_hi;

    int llo = 0, lhi = 0;
    for (int i = tid; i < BATCH; i += 256) {
        int id = ids[i];
        llo += (id < c);
        lhi += (id <= c);
    }
    ired[tid] = llo; __syncthreads();
    for (int s = 128; s > 0; s >>= 1) { if (tid < s) ired[tid] += ired[tid + s]; __syncthreads(); }
    if (tid == 0) s_lo = ired[0];
    __syncthreads();
    ired[tid] = lhi; __syncthreads();
    for (int s = 128; s > 0; s >>= 1) { if (tid < s) ired[tid] += ired[tid + s]; __syncthreads(); }
    if (tid == 0) s_hi = ired[0];
    __syncthreads();

    const int lo = s_lo, hi = s_hi, nn = hi - lo;

    // segment max
    float m = -INFINITY;
    for (int i = lo + tid; i < hi; i += 256) m = fmaxf(m, logits[i]);
    red[tid] = m; __syncthreads();
    for (int s = 128; s > 0; s >>= 1) { if (tid < s) red[tid] = fmaxf(red[tid], red[tid + s]); __syncthreads(); }
    const float segmax = red[0];
    __syncthreads();

    // exp + denom
    float ls = 0.f;
    for (int i = lo + tid; i < hi; i += 256) {
        float e = expf(logits[i] - segmax);
        wgt[i - lo] = e;
        ls += e;
    }
    red[tid] = ls; __syncthreads();
    for (int s = 128; s > 0; s >>= 1) { if (tid < s) red[tid] += red[tid + s]; __syncthreads(); }
    const float denom = red[0];
    __syncthreads();

    for (int i = tid; i < nn; i += 256) wgt[i] /= denom;
    __syncthreads();

    // aggr[h] = sum_k wgt[k]*emb[lo+k][h];  sc = aggr . clf_w
    float sc = 0.f;
    for (int h = tid; h < HID; h += 256) {
        float a = 0.f;
        for (int k = 0; k < nn; k++)
            a = fmaf(wgt[k], emb[(size_t)(lo + k) * HID + h], a);
        sc = fmaf(a, clf_w[h], sc);
    }
    red[tid] = sc; __syncthreads();
    for (int s = 128; s > 0; s >>= 1) { if (tid < s) red[tid] += red[tid + s]; __syncthreads(); }
    if (tid == 0) out[c] = 1.f / (1.f + expf(-(red[0] + clf_b[0])));
}

// ---------------- launch ----------------
extern "C" void kernel_launch(void* const* d_in, const int* in_sizes, int n_in,
                              void* d_out, int out_size)
{
    const float* data = (const float*)d_in[0];
    const int*   cid  = (const int*)d_in[1];
    const float* cw1 = (const float*)d_in[2];  const float* cb1 = (const float*)d_in[3];
    const float* cw2 = (const float*)d_in[4];  const float* cb2 = (const float*)d_in[5];
    const float* cw3 = (const float*)d_in[6];  const float* cb3 = (const float*)d_in[7];
    const float* cw4 = (const float*)d_in[8];  const float* cb4 = (const float*)d_in[9];
    const float* cw5 = (const float*)d_in[10]; const float* cb5 = (const float*)d_in[11];
    const float* fcw = (const float*)d_in[12]; const float* fcb = (const float*)d_in[13];
    const float* aw1 = (const float*)d_in[14]; const float* ab1 = (const float*)d_in[15];
    const float* aw2 = (const float*)d_in[16]; const float* ab2 = (const float*)d_in[17];
    const float* clw = (const float*)d_in[18]; const float* clb = (const float*)d_in[19];
    float* out = (float*)d_out;

    float *a1, *a2, *a3, *a4, *a5, *emb, *lg;
    cudaGetSymbolAddress((void**)&a1, g_act1);
    cudaGetSymbolAddress((void**)&a2, g_act2);
    cudaGetSymbolAddress((void**)&a3, g_act3);
    cudaGetSymbolAddress((void**)&a4, g_act4);
    cudaGetSymbolAddress((void**)&a5, g_act5);
    cudaGetSymbolAddress((void**)&emb, g_emb);
    cudaGetSymbolAddress((void**)&lg, g_logits);

    // dynamic smem sizes (bytes): ins = CIN*PATCH*(PATCH+1), w = COUT_BLK*CIN*25
    const int SM1 = (3 * 36 * 37 + 8 * 3 * 25) * 4;     // 18384
    const int SM2 = (8 * 36 * 37 + 16 * 8 * 25) * 4;    // 55424
    const int SM3 = (16 * 36 * 37 + 16 * 16 * 25) * 4;  // 110848
    const int SM4 = (32 * 20 * 21 + 32 * 32 * 25) * 4;  // 156160
    const int SM5 = (64 * 12 * 13) * 4;                 // 39936

    cudaFuncSetAttribute((const void*)conv_pool_relu<8, 16, 8, 16, 64, true, 512>,
                         cudaFuncAttributeMaxDynamicSharedMemorySize, SM2);
    cudaFuncSetAttribute((const void*)conv_pool_relu<16, 16, 8, 16, 32, true, 512>,
                         cudaFuncAttributeMaxDynamicSharedMemorySize, SM3);
    cudaFuncSetAttribute((const void*)conv_pool_relu<32, 32, 8, 8, 16, true, 256>,
                         cudaFuncAttributeMaxDynamicSharedMemorySize, SM4);

    // L1: 3->8, 128->64.  grid (4x4 tiles, 1, 512)
    conv_pool_relu<3, 8, 8, 16, 128, true, 256>
        <<<dim3(16, 1, 512), 256, SM1>>>(data, cw1, cb1, a1, 8);
    // L2: 8->16, 64->32.  grid (2x2 tiles, 1, 512)
    conv_pool_relu<8, 16, 8, 16, 64, true, 512>
        <<<dim3(4, 1, 512), 512, SM2>>>(a1, cw2, cb2, a2, 16);
    // L3: 16->32, 32->16. grid (1, 2 cout-groups, 512)
    conv_pool_relu<16, 16, 8, 16, 32, true, 512>
        <<<dim3(1, 2, 512), 512, SM3>>>(a2, cw3, cb3, a3, 32);
    // L4: 32->64, 16->8.  grid (1, 2, 512)
    conv_pool_relu<32, 32, 8, 8, 16, true, 256>
        <<<dim3(1, 2, 512), 256, SM4>>>(a3, cw4, cb4, a4, 64);
    // L5: 64->128, 8->4.  grid (1, 1, 512); weights via L2 (__ldg)
    conv_pool_relu<64, 128, 8, 4, 8, false, 256>
        <<<dim3(1, 1, 512), 256, SM5>>>(a4, cw5, cb5, a5, 128);

    // FC: (512x2048)@(1024x2048)^T
    fc_gemm<<<dim3(16, 8), 256>>>(a5, fcw, fcb, emb);

    // attention logits
    attention_kernel<<<64, 128>>>(emb, aw1, ab1, aw2, ab2, lg);

    // segment softmax + aggregate + classifier
    segment_head<<<64, 256>>>(lg, cid, emb, clw, clb, out);
}

// round 4
// speedup vs baseline: 1.0027x; 1.0011x over previous
#include <cuda_runtime.h>
#include <math.h>

// Problem constants
#define BATCH 512
#define NSEG 64
#define HID 1024
#define ATTD 128

// ---------------- scratch (device globals; no allocation allowed) ----------------
__device__ float g_act1[512 * 8 * 64 * 64];   // after layer1 (pooled)
__device__ float g_act2[512 * 16 * 32 * 32];
__device__ float g_act3[512 * 32 * 16 * 16];
__device__ float g_act4[512 * 64 * 8 * 8];
__device__ float g_act5[512 * 128 * 4 * 4];   // = emb input (512 x 2048)
__device__ float g_emb[512 * 1024];
__device__ float g_logits[512];

// ---------------- fused conv(5x5,pad2) + maxpool(2) + relu ----------------
// Each thread: one pooled output pixel x NCO output channels.
// acc[4][NCO]: 2x2 conv window accumulated simultaneously so each weight
// load is reused 4x and each input load NCO x.
template <int CIN, int COUT_BLK, int NCO, int TP, int IN_HW, bool W_SMEM, int NTHREADS>
__global__ __launch_bounds__(NTHREADS)
void conv_pool_relu(const float* __restrict__ in, const float* __restrict__ w,
                    const float* __restrict__ bias, float* __restrict__ out,
                    int cout_total)
{
    constexpr int OUT_HW = IN_HW / 2;
    constexpr int TILES  = OUT_HW / TP;
    constexpr int PATCH  = 2 * TP + 4;
    constexpr int PS     = PATCH + 1;            // odd row stride -> no LDS conflicts
    constexpr int CG     = COUT_BLK / NCO;

    extern __shared__ float smem[];
    float* ins = smem;                            // CIN * PATCH * PS
    float* wsm = smem + CIN * PATCH * PS;         // COUT_BLK * CIN * 25 (if W_SMEM)

    const int tid     = threadIdx.x;
    const int n       = blockIdx.z;
    const int co0_blk = blockIdx.y * COUT_BLK;
    const int ty      = blockIdx.x / TILES;
    const int tx      = blockIdx.x % TILES;
    const int y0      = ty * TP * 2 - 2;          // patch origin in input coords
    const int x0      = tx * TP * 2 - 2;

    // stage input patch (zero-padded halo)
    const float* inb = in + (size_t)n * CIN * IN_HW * IN_HW;
    for (int idx = tid; idx < CIN * PATCH * PATCH; idx += NTHREADS) {
        int ci  = idx / (PATCH * PATCH);
        int rem = idx % (PATCH * PATCH);
        int r   = rem / PATCH;
        int cc  = rem % PATCH;
        int gy  = y0 + r, gx = x0 + cc;
        float v = 0.f;
        if (gy >= 0 && gy < IN_HW && gx >= 0 && gx < IN_HW)
            v = inb[(ci * IN_HW + gy) * IN_HW + gx];
        ins[(ci * PATCH + r) * PS + cc] = v;
    }
    if (W_SMEM) {
        const float* wb = w + (size_t)co0_blk * CIN * 25;
        for (int idx = tid; idx < COUT_BLK * CIN * 25; idx += NTHREADS)
            wsm[idx] = wb[idx];
    }
    __syncthreads();

    const int ppx = tid % TP;
    const int ppy = (tid / TP) % TP;
    const int cg  = tid / (TP * TP);
    const int co0 = co0_blk + cg * NCO;

    float acc[4][NCO];
#pragma unroll
    for (int c = 0; c < NCO; c++) {
        float bv = bias[co0 + c];
        acc[0][c] = bv; acc[1][c] = bv; acc[2][c] = bv; acc[3][c] = bv;
    }

#pragma unroll 1
    for (int ci = 0; ci < CIN; ci++) {
        const float* insc = ins + ci * PATCH * PS;
#pragma unroll
        for (int ky = 0; ky < 5; ky++) {
#pragma unroll
            for (int kx = 0; kx < 5; kx++) {
                float wv[NCO];
#pragma unroll
                for (int c = 0; c < NCO; c++) {
                    if (W_SMEM)
                        wv[c] = wsm[((cg * NCO + c) * CIN + ci) * 25 + ky * 5 + kx];
                    else
                        wv[c] = __ldg(&w[((size_t)(co0 + c) * CIN + ci) * 25 + ky * 5 + kx]);
                }
#pragma unroll
                for (int cy = 0; cy < 2; cy++)
#pragma unroll
                for (int cx = 0; cx < 2; cx++) {
                    float v = insc[(2 * ppy + cy + ky) * PS + (2 * ppx + cx + kx)];
#pragma unroll
                    for (int c = 0; c < NCO; c++)
                        acc[cy * 2 + cx][c] = fmaf(v, wv[c], acc[cy * 2 + cx][c]);
                }
            }
        }
    }

    const int oy = ty * TP + ppy;
    const int ox = tx * TP + ppx;
    float* outb = out + (size_t)n * cout_total * OUT_HW * OUT_HW;
#pragma unroll
    for (int c = 0; c < NCO; c++) {
        float m = fmaxf(fmaxf(acc[0][c], acc[1][c]), fmaxf(acc[2][c], acc[3][c]));
        m = fmaxf(m, 0.f);
        outb[((size_t)(co0 + c) * OUT_HW + oy) * OUT_HW + ox] = m;
    }
}

// ---------------- FC: emb = act5(512x2048) @ fc_w(1024x2048)^T + fc_b ----------------
__global__ __launch_bounds__(256)
void fc_gemm(const float* __restrict__ A, const float* __restrict__ W,
             const float* __restrict__ bias, float* __restrict__ C)
{
    constexpr int N = 1024, K = 2048, BM = 64, BN = 64, BK = 16;
    __shared__ float As[BK][BM];
    __shared__ float Ws[BK][BN];

    const int tid = threadIdx.x;
    const int bm = blockIdx.y * BM, bn = blockIdx.x * BN;
    const int tx = tid % 16, ty = tid / 16;
    const int lr = tid / 4, lc = tid % 4;   // staging coords

    float acc[4][4] = {};

    for (int k0 = 0; k0 < K; k0 += BK) {
        float4 a4 = *(const float4*)&A[(size_t)(bm + lr) * K + k0 + lc * 4];
        float4 w4 = *(const float4*)&W[(size_t)(bn + lr) * K + k0 + lc * 4];
        As[lc * 4 + 0][lr] = a4.x; As[lc * 4 + 1][lr] = a4.y;
        As[lc * 4 + 2][lr] = a4.z; As[lc * 4 + 3][lr] = a4.w;
        Ws[lc * 4 + 0][lr] = w4.x; Ws[lc * 4 + 1][lr] = w4.y;
        Ws[lc * 4 + 2][lr] = w4.z; Ws[lc * 4 + 3][lr] = w4.w;
        __syncthreads();
#pragma unroll
        for (int kk = 0; kk < BK; kk++) {
            float4 av = *(const float4*)&As[kk][ty * 4];
            float4 wv = *(const float4*)&Ws[kk][tx * 4];
            acc[0][0] += av.x * wv.x; acc[0][1] += av.x * wv.y; acc[0][2] += av.x * wv.z; acc[0][3] += av.x * wv.w;
            acc[1][0] += av.y * wv.x; acc[1][1] += av.y * wv.y; acc[1][2] += av.y * wv.z; acc[1][3] += av.y * wv.w;
            acc[2][0] += av.z * wv.x; acc[2][1] += av.z * wv.y; acc[2][2] += av.z * wv.z; acc[2][3] += av.z * wv.w;
            acc[3][0] += av.w * wv.x; acc[3][1] += av.w * wv.y; acc[3][2] += av.w * wv.z; acc[3][3] += av.w * wv.w;
        }
        __syncthreads();
    }

#pragma unroll
    for (int i = 0; i < 4; i++)
#pragma unroll
        for (int j = 0; j < 4; j++)
            C[(size_t)(bm + ty * 4 + i) * N + bn + tx * 4 + j] = acc[i][j] + bias[bn + tx * 4 + j];
}

// ---------------- attention logits: tanh(emb@W1^T+b1)@W2^T+b2 ----------------
// One block handles 8 batch rows; 128 threads = 128 attention units.
__global__ __launch_bounds__(128)
void attention_kernel(const float* __restrict__ emb, const float* __restrict__ w1,
                      const float* __restrict__ b1, const float* __restrict__ w2,
                      const float* __restrict__ b2, float* __restrict__ logits)
{
    __shared__ float es[8][HID];      // 32 KB
    __shared__ float red[128];
    const int tid = threadIdx.x;
    const int r0 = blockIdx.x * 8;

    for (int idx = tid; idx < 8 * HID; idx += 128)
        es[idx / HID][idx % HID] = emb[(size_t)(r0 + idx / HID) * HID + idx % HID];
    __syncthreads();

    const int j = tid;
    float acc[8];
    float bj = b1[j];
#pragma unroll
    for (int r = 0; r < 8; r++) acc[r] = bj;

    for (int k = 0; k < HID; k++) {
        float wv = w1[(size_t)j * HID + k];
#pragma unroll
        for (int r = 0; r < 8; r++) acc[r] = fmaf(es[r][k], wv, acc[r]);
    }

    const float w2j = w2[j];
    for (int r = 0; r < 8; r++) {
        red[tid] = tanhf(acc[r]) * w2j;
        __syncthreads();
        for (int s = 64; s > 0; s >>= 1) {
            if (tid < s) red[tid] += red[tid + s];
            __syncthreads();
        }
        if (tid == 0) logits[r0 + r] = red[0] + b2[0];
        __syncthreads();
    }
}

// ---------------- segment softmax + weighted aggregate + classifier ----------------
// case_ids are sorted; one block per segment.
__global__ __launch_bounds__(256)
void segment_head(const float* __restrict__ logits, const int* __restrict__ ids,
                  const float* __restrict__ emb, const float* __restrict__ clf_w,
                  const float* __restrict__ clf_b, float* __restrict__ out)
{
    const int c = blockIdx.x, tid = threadIdx.x;
    __shared__ float red[256];
    __shared__ int ired[256];
    __shared__ float wgt[512];
    __shared__ int s_lo, s_hi;

    int llo = 0, lhi = 0;
    for (int i = tid; i < BATCH; i += 256) {
        int id = ids[i];
        llo += (id < c);
        lhi += (id <= c);
    }
    ired[tid] = llo; __syncthreads();
    for (int s = 128; s > 0; s >>= 1) { if (tid < s) ired[tid] += ired[tid + s]; __syncthreads(); }
    if (tid == 0) s_lo = ired[0];
    __syncthreads();
    ired[tid] = lhi; __syncthreads();
    for (int s = 128; s > 0; s >>= 1) { if (tid < s) ired[tid] += ired[tid + s]; __syncthreads(); }
    if (tid == 0) s_hi = ired[0];
    __syncthreads();

    const int lo = s_lo, hi = s_hi, nn = hi - lo;

    // segment max
    float m = -INFINITY;
    for (int i = lo + tid; i < hi; i += 256) m = fmaxf(m, logits[i]);
    red[tid] = m; __syncthreads();
    for (int s = 128; s > 0; s >>= 1) { if (tid < s) red[tid] = fmaxf(red[tid], red[tid + s]); __syncthreads(); }
    const float segmax = red[0];
    __syncthreads();

    // exp + denom
    float ls = 0.f;
    for (int i = lo + tid; i < hi; i += 256) {
        float e = expf(logits[i] - segmax);
        wgt[i - lo] = e;
        ls += e;
    }
    red[tid] = ls; __syncthreads();
    for (int s = 128; s > 0; s >>= 1) { if (tid < s) red[tid] += red[tid + s]; __syncthreads(); }
    const float denom = red[0];
    __syncthreads();

    for (int i = tid; i < nn; i += 256) wgt[i] /= denom;
    __syncthreads();

    // aggr[h] = sum_k wgt[k]*emb[lo+k][h];  sc = aggr . clf_w
    float sc = 0.f;
    for (int h = tid; h < HID; h += 256) {
        float a = 0.f;
        for (int k = 0; k < nn; k++)
            a = fmaf(wgt[k], emb[(size_t)(lo + k) * HID + h], a);
        sc = fmaf(a, clf_w[h], sc);
    }
    red[tid] = sc; __syncthreads();
    for (int s = 128; s > 0; s >>= 1) { if (tid < s) red[tid] += red[tid + s]; __syncthreads(); }
    if (tid == 0) out[c] = 1.f / (1.f + expf(-(red[0] + clf_b[0])));
}

// ---------------- launch ----------------
extern "C" void kernel_launch(void* const* d_in, const int* in_sizes, int n_in,
                              void* d_out, int out_size)
{
    const float* data = (const float*)d_in[0];
    const int*   cid  = (const int*)d_in[1];
    const float* cw1 = (const float*)d_in[2];  const float* cb1 = (const float*)d_in[3];
    const float* cw2 = (const float*)d_in[4];  const float* cb2 = (const float*)d_in[5];
    const float* cw3 = (const float*)d_in[6];  const float* cb3 = (const float*)d_in[7];
    const float* cw4 = (const float*)d_in[8];  const float* cb4 = (const float*)d_in[9];
    const float* cw5 = (const float*)d_in[10]; const float* cb5 = (const float*)d_in[11];
    const float* fcw = (const float*)d_in[12]; const float* fcb = (const float*)d_in[13];
    const float* aw1 = (const float*)d_in[14]; const float* ab1 = (const float*)d_in[15];
    const float* aw2 = (const float*)d_in[16]; const float* ab2 = (const float*)d_in[17];
    const float* clw = (const float*)d_in[18]; const float* clb = (const float*)d_in[19];
    float* out = (float*)d_out;

    float *a1, *a2, *a3, *a4, *a5, *emb, *lg;
    cudaGetSymbolAddress((void**)&a1, g_act1);
    cudaGetSymbolAddress((void**)&a2, g_act2);
    cudaGetSymbolAddress((void**)&a3, g_act3);
    cudaGetSymbolAddress((void**)&a4, g_act4);
    cudaGetSymbolAddress((void**)&a5, g_act5);
    cudaGetSymbolAddress((void**)&emb, g_emb);
    cudaGetSymbolAddress((void**)&lg, g_logits);

    // dynamic smem sizes (bytes): ins = CIN*PATCH*(PATCH+1), w = COUT_BLK*CIN*25
    const int SM1 = (3 * 36 * 37 + 8 * 3 * 25) * 4;     // 18384
    const int SM2 = (8 * 36 * 37 + 16 * 8 * 25) * 4;    // 55424
    const int SM3 = (16 * 36 * 37 + 16 * 16 * 25) * 4;  // 110848
    const int SM4 = (32 * 20 * 21 + 32 * 32 * 25) * 4;  // 156160
    const int SM5 = (64 * 12 * 13) * 4;                 // 39936

    cudaFuncSetAttribute((const void*)conv_pool_relu<8, 16, 8, 16, 64, true, 512>,
                         cudaFuncAttributeMaxDynamicSharedMemorySize, SM2);
    cudaFuncSetAttribute((const void*)conv_pool_relu<16, 16, 8, 16, 32, true, 512>,
                         cudaFuncAttributeMaxDynamicSharedMemorySize, SM3);
    cudaFuncSetAttribute((const void*)conv_pool_relu<32, 32, 8, 8, 16, true, 256>,
                         cudaFuncAttributeMaxDynamicSharedMemorySize, SM4);

    // L1: 3->8, 128->64.  grid (4x4 tiles, 1, 512)
    conv_pool_relu<3, 8, 8, 16, 128, true, 256>
        <<<dim3(16, 1, 512), 256, SM1>>>(data, cw1, cb1, a1, 8);
    // L2: 8->16, 64->32.  grid (2x2 tiles, 1, 512)
    conv_pool_relu<8, 16, 8, 16, 64, true, 512>
        <<<dim3(4, 1, 512), 512, SM2>>>(a1, cw2, cb2, a2, 16);
    // L3: 16->32, 32->16. grid (1, 2 cout-groups, 512)
    conv_pool_relu<16, 16, 8, 16, 32, true, 512>
        <<<dim3(1, 2, 512), 512, SM3>>>(a2, cw3, cb3, a3, 32);
    // L4: 32->64, 16->8.  grid (1, 2, 512)
    conv_pool_relu<32, 32, 8, 8, 16, true, 256>
        <<<dim3(1, 2, 512), 256, SM4>>>(a3, cw4, cb4, a4, 64);
    // L5: 64->128, 8->4.  grid (1, 1, 512); weights via L2 (__ldg)
    conv_pool_relu<64, 128, 8, 4, 8, false, 256>
        <<<dim3(1, 1, 512), 256, SM5>>>(a4, cw5, cb5, a5, 128);

    // FC: (512x2048)@(1024x2048)^T
    fc_gemm<<<dim3(16, 8), 256>>>(a5, fcw, fcb, emb);

    // attention logits
    attention_kernel<<<64, 128>>>(emb, aw1, ab1, aw2, ab2, lg);

    // segment softmax + aggregate + classifier
    segment_head<<<64, 256>>>(lg, cid, emb, clw, clb, out);
}

// round 5
// speedup vs baseline: 1.0027x; 1.0000x over previous
#include <cuda_runtime.h>
#include <math.h>

// Problem constants
#define BATCH 512
#define NSEG 64
#define HID 1024
#define ATTD 128

// ---------------- scratch (device globals; no allocation allowed) ----------------
__device__ float g_act1[512 * 8 * 64 * 64];   // after layer1 (pooled)
__device__ float g_act2[512 * 16 * 32 * 32];
__device__ float g_act3[512 * 32 * 16 * 16];
__device__ float g_act4[512 * 64 * 8 * 8];
__device__ float g_act5[512 * 128 * 4 * 4];   // = emb input (512 x 2048)
__device__ float g_emb[512 * 1024];
__device__ float g_logits[512];

// ---------------- fused conv(5x5,pad2) + maxpool(2) + relu ----------------
// Each thread: one pooled output pixel x NCO output channels.
// acc[4][NCO]: 2x2 conv window accumulated simultaneously so each weight
// load is reused 4x and each input load NCO x.
template <int CIN, int COUT_BLK, int NCO, int TP, int IN_HW, bool W_SMEM, int NTHREADS>
__global__ __launch_bounds__(NTHREADS)
void conv_pool_relu(const float* __restrict__ in, const float* __restrict__ w,
                    const float* __restrict__ bias, float* __restrict__ out,
                    int cout_total)
{
    constexpr int OUT_HW = IN_HW / 2;
    constexpr int TILES  = OUT_HW / TP;
    constexpr int PATCH  = 2 * TP + 4;
    constexpr int PS     = PATCH + 1;            // odd row stride -> no LDS conflicts
    constexpr int CG     = COUT_BLK / NCO;

    extern __shared__ float smem[];
    float* ins = smem;                            // CIN * PATCH * PS
    float* wsm = smem + CIN * PATCH * PS;         // COUT_BLK * CIN * 25 (if W_SMEM)

    const int tid     = threadIdx.x;
    const int n       = blockIdx.z;
    const int co0_blk = blockIdx.y * COUT_BLK;
    const int ty      = blockIdx.x / TILES;
    const int tx      = blockIdx.x % TILES;
    const int y0      = ty * TP * 2 - 2;          // patch origin in input coords
    const int x0      = tx * TP * 2 - 2;

    // stage input patch (zero-padded halo)
    const float* inb = in + (size_t)n * CIN * IN_HW * IN_HW;
    for (int idx = tid; idx < CIN * PATCH * PATCH; idx += NTHREADS) {
        int ci  = idx / (PATCH * PATCH);
        int rem = idx % (PATCH * PATCH);
        int r   = rem / PATCH;
        int cc  = rem % PATCH;
        int gy  = y0 + r, gx = x0 + cc;
        float v = 0.f;
        if (gy >= 0 && gy < IN_HW && gx >= 0 && gx < IN_HW)
            v = inb[(ci * IN_HW + gy) * IN_HW + gx];
        ins[(ci * PATCH + r) * PS + cc] = v;
    }
    if (W_SMEM) {
        const float* wb = w + (size_t)co0_blk * CIN * 25;
        for (int idx = tid; idx < COUT_BLK * CIN * 25; idx += NTHREADS)
            wsm[idx] = wb[idx];
    }
    __syncthreads();

    const int ppx = tid % TP;
    const int ppy = (tid / TP) % TP;
    const int cg  = tid / (TP * TP);
    const int co0 = co0_blk + cg * NCO;

    float acc[4][NCO];
#pragma unroll
    for (int c = 0; c < NCO; c++) {
        float bv = bias[co0 + c];
        acc[0][c] = bv; acc[1][c] = bv; acc[2][c] = bv; acc[3][c] = bv;
    }

#pragma unroll 1
    for (int ci = 0; ci < CIN; ci++) {
        const float* insc = ins + ci * PATCH * PS;
#pragma unroll
        for (int ky = 0; ky < 5; ky++) {
#pragma unroll
            for (int kx = 0; kx < 5; kx++) {
                float wv[NCO];
#pragma unroll
                for (int c = 0; c < NCO; c++) {
                    if (W_SMEM)
                        wv[c] = wsm[((cg * NCO + c) * CIN + ci) * 25 + ky * 5 + kx];
                    else
                        wv[c] = __ldg(&w[((size_t)(co0 + c) * CIN + ci) * 25 + ky * 5 + kx]);
                }
#pragma unroll
                for (int cy = 0; cy < 2; cy++)
#pragma unroll
                for (int cx = 0; cx < 2; cx++) {
                    float v = insc[(2 * ppy + cy + ky) * PS + (2 * ppx + cx + kx)];
#pragma unroll
                    for (int c = 0; c < NCO; c++)
                        acc[cy * 2 + cx][c] = fmaf(v, wv[c], acc[cy * 2 + cx][c]);
                }
            }
        }
    }

    const int oy = ty * TP + ppy;
    const int ox = tx * TP + ppx;
    float* outb = out + (size_t)n * cout_total * OUT_HW * OUT_HW;
#pragma unroll
    for (int c = 0; c < NCO; c++) {
        float m = fmaxf(fmaxf(acc[0][c], acc[1][c]), fmaxf(acc[2][c], acc[3][c]));
        m = fmaxf(m, 0.f);
        outb[((size_t)(co0 + c) * OUT_HW + oy) * OUT_HW + ox] = m;
    }
}

// ---------------- FC: emb = act5(512x2048) @ fc_w(1024x2048)^T + fc_b ----------------
__global__ __launch_bounds__(256)
void fc_gemm(const float* __restrict__ A, const float* __restrict__ W,
             const float* __restrict__ bias, float* __restrict__ C)
{
    constexpr int N = 1024, K = 2048, BM = 64, BN = 64, BK = 16;
    __shared__ float As[BK][BM];
    __shared__ float Ws[BK][BN];

    const int tid = threadIdx.x;
    const int bm = blockIdx.y * BM, bn = blockIdx.x * BN;
    const int tx = tid % 16, ty = tid / 16;
    const int lr = tid / 4, lc = tid % 4;   // staging coords

    float acc[4][4] = {};

    for (int k0 = 0; k0 < K; k0 += BK) {
        float4 a4 = *(const float4*)&A[(size_t)(bm + lr) * K + k0 + lc * 4];
        float4 w4 = *(const float4*)&W[(size_t)(bn + lr) * K + k0 + lc * 4];
        As[lc * 4 + 0][lr] = a4.x; As[lc * 4 + 1][lr] = a4.y;
        As[lc * 4 + 2][lr] = a4.z; As[lc * 4 + 3][lr] = a4.w;
        Ws[lc * 4 + 0][lr] = w4.x; Ws[lc * 4 + 1][lr] = w4.y;
        Ws[lc * 4 + 2][lr] = w4.z; Ws[lc * 4 + 3][lr] = w4.w;
        __syncthreads();
#pragma unroll
        for (int kk = 0; kk < BK; kk++) {
            float4 av = *(const float4*)&As[kk][ty * 4];
            float4 wv = *(const float4*)&Ws[kk][tx * 4];
            acc[0][0] += av.x * wv.x; acc[0][1] += av.x * wv.y; acc[0][2] += av.x * wv.z; acc[0][3] += av.x * wv.w;
            acc[1][0] += av.y * wv.x; acc[1][1] += av.y * wv.y; acc[1][2] += av.y * wv.z; acc[1][3] += av.y * wv.w;
            acc[2][0] += av.z * wv.x; acc[2][1] += av.z * wv.y; acc[2][2] += av.z * wv.z; acc[2][3] += av.z * wv.w;
            acc[3][0] += av.w * wv.x; acc[3][1] += av.w * wv.y; acc[3][2] += av.w * wv.z; acc[3][3] += av.w * wv.w;
        }
        __syncthreads();
    }

#pragma unroll
    for (int i = 0; i < 4; i++)
#pragma unroll
        for (int j = 0; j < 4; j++)
            C[(size_t)(bm + ty * 4 + i) * N + bn + tx * 4 + j] = acc[i][j] + bias[bn + tx * 4 + j];
}

// ---------------- attention logits: tanh(emb@W1^T+b1)@W2^T+b2 ----------------
// One block handles 8 batch rows; 128 threads = 128 attention units.
__global__ __launch_bounds__(128)
void attention_kernel(const float* __restrict__ emb, const float* __restrict__ w1,
                      const float* __restrict__ b1, const float* __restrict__ w2,
                      const float* __restrict__ b2, float* __restrict__ logits)
{
    __shared__ float es[8][HID];      // 32 KB
    __shared__ float red[128];
    const int tid = threadIdx.x;
    const int r0 = blockIdx.x * 8;

    for (int idx = tid; idx < 8 * HID; idx += 128)
        es[idx / HID][idx % HID] = emb[(size_t)(r0 + idx / HID) * HID + idx % HID];
    __syncthreads();

    const int j = tid;
    float acc[8];
    float bj = b1[j];
#pragma unroll
    for (int r = 0; r < 8; r++) acc[r] = bj;

    for (int k = 0; k < HID; k++) {
        float wv = w1[(size_t)j * HID + k];
#pragma unroll
        for (int r = 0; r < 8; r++) acc[r] = fmaf(es[r][k], wv, acc[r]);
    }

    const float w2j = w2[j];
    for (int r = 0; r < 8; r++) {
        red[tid] = tanhf(acc[r]) * w2j;
        __syncthreads();
        for (int s = 64; s > 0; s >>= 1) {
            if (tid < s) red[tid] += red[tid + s];
            __syncthreads();
        }
        if (tid == 0) logits[r0 + r] = red[0] + b2[0];
        __syncthreads();
    }
}

// ---------------- segment softmax + weighted aggregate + classifier ----------------
// case_ids are sorted; one block per segment.
__global__ __launch_bounds__(256)
void segment_head(const float* __restrict__ logits, const int* __restrict__ ids,
                  const float* __restrict__ emb, const float* __restrict__ clf_w,
                  const float* __restrict__ clf_b, float* __restrict__ out)
{
    const int c = blockIdx.x, tid = threadIdx.x;
    __shared__ float red[256];
    __shared__ int ired[256];
    __shared__ float wgt[512];
    __shared__ int s_lo, s_hi;

    int llo = 0, lhi = 0;
    for (int i = tid; i < BATCH; i += 256) {
        int id = ids[i];
        llo += (id < c);
        lhi += (id <= c);
    }
    ired[tid] = llo; __syncthreads();
    for (int s = 128; s > 0; s >>= 1) { if (tid < s) ired[tid] += ired[tid + s]; __syncthreads(); }
    if (tid == 0) s_lo = ired[0];
    __syncthreads();
    ired[tid] = lhi; __syncthreads();
    for (int s = 128; s > 0; s >>= 1) { if (tid < s) ired[tid] += ired[tid + s]; __syncthreads(); }
    if (tid == 0) s_hi = ired[0];
    __syncthreads();

    const int lo = s_lo, hi = s_hi, nn = hi - lo;

    // segment max
    float m = -INFINITY;
    for (int i = lo + tid; i < hi; i += 256) m = fmaxf(m, logits[i]);
    red[tid] = m; __syncthreads();
    for (int s = 128; s > 0; s >>= 1) { if (tid < s) red[tid] = fmaxf(red[tid], red[tid + s]); __syncthreads(); }
    const float segmax = red[0];
    __syncthreads();

    // exp + denom
    float ls = 0.f;
    for (int i = lo + tid; i < hi; i += 256) {
        float e = expf(logits[i] - segmax);
        wgt[i - lo] = e;
        ls += e;
    }
    red[tid] = ls; __syncthreads();
    for (int s = 128; s > 0; s >>= 1) { if (tid < s) red[tid] += red[tid + s]; __syncthreads(); }
    const float denom = red[0];
    __syncthreads();

    for (int i = tid; i < nn; i += 256) wgt[i] /= denom;
    __syncthreads();

    // aggr[h] = sum_k wgt[k]*emb[lo+k][h];  sc = aggr . clf_w
    float sc = 0.f;
    for (int h = tid; h < HID; h += 256) {
        float a = 0.f;
        for (int k = 0; k < nn; k++)
            a = fmaf(wgt[k], emb[(size_t)(lo + k) * HID + h], a);
        sc = fmaf(a, clf_w[h], sc);
    }
    red[tid] = sc; __syncthreads();
    for (int s = 128; s > 0; s >>= 1) { if (tid < s) red[tid] += red[tid + s]; __syncthreads(); }
    if (tid == 0) out[c] = 1.f / (1.f + expf(-(red[0] + clf_b[0])));
}

// ---------------- launch ----------------
extern "C" void kernel_launch(void* const* d_in, const int* in_sizes, int n_in,
                              void* d_out, int out_size)
{
    const float* data = (const float*)d_in[0];
    const int*   cid  = (const int*)d_in[1];
    const float* cw1 = (const float*)d_in[2];  const float* cb1 = (const float*)d_in[3];
    const float* cw2 = (const float*)d_in[4];  const float* cb2 = (const float*)d_in[5];
    const float* cw3 = (const float*)d_in[6];  const float* cb3 = (const float*)d_in[7];
    const float* cw4 = (const float*)d_in[8];  const float* cb4 = (const float*)d_in[9];
    const float* cw5 = (const float*)d_in[10]; const float* cb5 = (const float*)d_in[11];
    const float* fcw = (const float*)d_in[12]; const float* fcb = (const float*)d_in[13];
    const float* aw1 = (const float*)d_in[14]; const float* ab1 = (const float*)d_in[15];
    const float* aw2 = (const float*)d_in[16]; const float* ab2 = (const float*)d_in[17];
    const float* clw = (const float*)d_in[18]; const float* clb = (const float*)d_in[19];
    float* out = (float*)d_out;

    float *a1, *a2, *a3, *a4, *a5, *emb, *lg;
    cudaGetSymbolAddress((void**)&a1, g_act1);
    cudaGetSymbolAddress((void**)&a2, g_act2);
    cudaGetSymbolAddress((void**)&a3, g_act3);
    cudaGetSymbolAddress((void**)&a4, g_act4);
    cudaGetSymbolAddress((void**)&a5, g_act5);
    cudaGetSymbolAddress((void**)&emb, g_emb);
    cudaGetSymbolAddress((void**)&lg, g_logits);

    // dynamic smem sizes (bytes): ins = CIN*PATCH*(PATCH+1), w = COUT_BLK*CIN*25
    const int SM1 = (3 * 36 * 37 + 8 * 3 * 25) * 4;     // 18384
    const int SM2 = (8 * 36 * 37 + 16 * 8 * 25) * 4;    // 55424
    const int SM3 = (16 * 36 * 37 + 16 * 16 * 25) * 4;  // 110848
    const int SM4 = (32 * 20 * 21 + 32 * 32 * 25) * 4;  // 156160
    const int SM5 = (64 * 12 * 13) * 4;                 // 39936

    cudaFuncSetAttribute((const void*)conv_pool_relu<8, 16, 8, 16, 64, true, 512>,
                         cudaFuncAttributeMaxDynamicSharedMemorySize, SM2);
    cudaFuncSetAttribute((const void*)conv_pool_relu<16, 16, 8, 16, 32, true, 512>,
                         cudaFuncAttributeMaxDynamicSharedMemorySize, SM3);
    cudaFuncSetAttribute((const void*)conv_pool_relu<32, 32, 8, 8, 16, true, 256>,
                         cudaFuncAttributeMaxDynamicSharedMemorySize, SM4);

    // L1: 3->8, 128->64.  grid (4x4 tiles, 1, 512)
    conv_pool_relu<3, 8, 8, 16, 128, true, 256>
        <<<dim3(16, 1, 512), 256, SM1>>>(data, cw1, cb1, a1, 8);
    // L2: 8->16, 64->32.  grid (2x2 tiles, 1, 512)
    conv_pool_relu<8, 16, 8, 16, 64, true, 512>
        <<<dim3(4, 1, 512), 512, SM2>>>(a1, cw2, cb2, a2, 16);
    // L3: 16->32, 32->16. grid (1, 2 cout-groups, 512)
    conv_pool_relu<16, 16, 8, 16, 32, true, 512>
        <<<dim3(1, 2, 512), 512, SM3>>>(a2, cw3, cb3, a3, 32);
    // L4: 32->64, 16->8.  grid (1, 2, 512)
    conv_pool_relu<32, 32, 8, 8, 16, true, 256>
        <<<dim3(1, 2, 512), 256, SM4>>>(a3, cw4, cb4, a4, 64);
    // L5: 64->128, 8->4.  grid (1, 1, 512); weights via L2 (__ldg)
    conv_pool_relu<64, 128, 8, 4, 8, false, 256>
        <<<dim3(1, 1, 512), 256, SM5>>>(a4, cw5, cb5, a5, 128);

    // FC: (512x2048)@(1024x2048)^T
    fc_gemm<<<dim3(16, 8), 256>>>(a5, fcw, fcb, emb);

    // attention logits
    attention_kernel<<<64, 128>>>(emb, aw1, ab1, aw2, ab2, lg);

    // segment softmax + aggregate + classifier
    segment_head<<<64, 256>>>(lg, cid, emb, clw, clb, out);
}